// round 2
// baseline (speedup 1.0000x reference)
#include <cuda_runtime.h>
#include <cuda_fp16.h>
#include <cstdint>

// ---------------- constants ----------------
#define GRID_CTAS 148
#define THREADS   256
#define TILE_M    256
#define NROWS     1048576
#define NTILES    (NROWS / TILE_M)      // 4096

// smem byte offsets (from 1024-aligned dynamic base)
#define SM_MASK   0                     // 256 u32 row routing flags
#define SM_B1CAT  1024                  // 256 f32 layer-1 biases (concat)
#define SM_B2S    2048                  // 128 f32 layer-2 biases (b | c)
#define SM_B1     4096                  // W1cat fp16 [k=64][n=256] ld=264 -> 33792 B
#define SM_B2     (SM_B1 + 33792)       // W2cat fp16 [k=256][n=64] ld=72  -> 36864 B
#define SM_A1     (SM_B2 + 36864)       // obs tile fp16 [256][64] ld=72   -> 36864 B
#define SM_XS     (SM_A1 + 36864)       // obs tile fp32 staging [256][64] -> 65536 B
#define SM_END    (SM_XS + 65536)
#define SMEM_BYTES (SM_END + 1024)

#define LD1 264   // halfs per row of B1
#define LD2 72    // halfs per row of B2
#define LDA 72    // halfs per row of A1

// ---------------- ptx helpers ----------------
__device__ __forceinline__ uint32_t s2u(const void* p) {
    uint32_t a;
    asm("{ .reg .u64 t; cvta.to.shared.u64 t, %1; cvt.u32.u64 %0, t; }" : "=r"(a) : "l"(p));
    return a;
}
__device__ __forceinline__ void ldsm_x4(uint32_t* r, uint32_t addr) {
    asm volatile("ldmatrix.sync.aligned.m8n8.x4.shared.b16 {%0,%1,%2,%3}, [%4];"
                 : "=r"(r[0]), "=r"(r[1]), "=r"(r[2]), "=r"(r[3]) : "r"(addr));
}
__device__ __forceinline__ void ldsm_x4t(uint32_t* r, uint32_t addr) {
    asm volatile("ldmatrix.sync.aligned.m8n8.x4.trans.shared.b16 {%0,%1,%2,%3}, [%4];"
                 : "=r"(r[0]), "=r"(r[1]), "=r"(r[2]), "=r"(r[3]) : "r"(addr));
}
__device__ __forceinline__ void mma16816(float* d, const uint32_t* a, uint32_t b0, uint32_t b1) {
    asm volatile("mma.sync.aligned.m16n8k16.row.col.f32.f16.f16.f32 "
                 "{%0,%1,%2,%3}, {%4,%5,%6,%7}, {%8,%9}, {%0,%1,%2,%3};"
                 : "+f"(d[0]), "+f"(d[1]), "+f"(d[2]), "+f"(d[3])
                 : "r"(a[0]), "r"(a[1]), "r"(a[2]), "r"(a[3]), "r"(b0), "r"(b1));
}
__device__ __forceinline__ void cp16(uint32_t dst, const void* src) {
    asm volatile("cp.async.cg.shared.global [%0], [%1], 16;" :: "r"(dst), "l"(src));
}
#define CP_COMMIT() asm volatile("cp.async.commit_group;" ::: "memory")
#define CP_WAIT0()  asm volatile("cp.async.wait_group 0;" ::: "memory")

__device__ __forceinline__ uint32_t packh2(float x, float y) {
    __half2 h = __floats2half2_rn(x, y);
    return *reinterpret_cast<uint32_t*>(&h);
}

// ---------------- kernel ----------------
extern "C" __global__ void __launch_bounds__(THREADS, 1)
STAR_moe_mlp_kernel(
    const float* __restrict__ obs,
    const float* __restrict__ W1b, const float* __restrict__ b1b,
    const float* __restrict__ W2b, const float* __restrict__ b2b,
    const float* __restrict__ W1c, const float* __restrict__ b1c,
    const float* __restrict__ W2c, const float* __restrict__ b2c,
    const float* __restrict__ W1p, const float* __restrict__ b1p,
    const float* __restrict__ W2p, const float* __restrict__ b2p,
    float* __restrict__ out)
{
    extern __shared__ char smem_raw[];
    uint32_t sb0 = s2u(smem_raw);
    uint32_t sb  = (sb0 + 1023u) & ~1023u;
    char* smb = smem_raw + (sb - sb0);

    const int tid = threadIdx.x;
    const int wid = tid >> 5, l = tid & 31;
    const int wrow = wid * 32;                 // warp's row base within tile

    uint32_t* msk   = reinterpret_cast<uint32_t*>(smb + SM_MASK);
    float*    b1cat = reinterpret_cast<float*>(smb + SM_B1CAT);
    float*    b2s   = reinterpret_cast<float*>(smb + SM_B2S);

    // ---- one-time setup: fused weights (fp16) + biases into SMEM ----
    for (int idx = tid; idx < 64 * 256; idx += THREADS) {       // B1: [k=64][n=256]
        int k = idx >> 8, n = idx & 255;
        float w = (n < 128) ? W1b[k * 128 + n] * W1p[k * 128 + n]
                            : W1c[k * 128 + (n - 128)] * W1p[k * 128 + (n - 128)];
        *reinterpret_cast<__half*>(smb + SM_B1 + (uint32_t)(k * LD1 + n) * 2) = __float2half_rn(w);
    }
    for (int idx = tid; idx < 256 * 64; idx += THREADS) {       // B2: [k=256][n=64]
        int k = idx >> 6, n = idx & 63;
        float w = (k < 128) ? W2b[k * 64 + n] * W2p[k * 64 + n]
                            : W2c[(k - 128) * 64 + n] * W2p[(k - 128) * 64 + n];
        *reinterpret_cast<__half*>(smb + SM_B2 + (uint32_t)(k * LD2 + n) * 2) = __float2half_rn(w);
    }
    for (int i = tid; i < 256; i += THREADS)
        b1cat[i] = (i < 128) ? b1b[i] + b1p[i] : b1c[i - 128] + b1p[i - 128];
    for (int i = tid; i < 128; i += THREADS)
        b2s[i] = (i < 64) ? b2b[i] + b2p[i] : b2c[i - 64] + b2p[i - 64];

    // ---- prologue: async-load first obs tile (fp32 staging) ----
    {
        const float4* g = reinterpret_cast<const float4*>(obs + (size_t)blockIdx.x * (TILE_M * 64));
        #pragma unroll
        for (int i = 0; i < 16; i++)
            cp16(sb + SM_XS + (uint32_t)(i * THREADS + tid) * 16, g + i * THREADS + tid);
    }
    CP_COMMIT();

    for (int it = 0;; it++) {
        int tile = blockIdx.x + it * GRID_CTAS;
        if (tile >= NTILES) break;

        // ---- convert staged fp32 -> fp16 A1 (+ routing masks) ----
        CP_WAIT0();
        __syncthreads();
        {
            const float4* xs = reinterpret_cast<const float4*>(smb + SM_XS);
            #pragma unroll
            for (int i = 0; i < 16; i++) {
                int f = i * THREADS + tid;
                float4 v = xs[f];
                int row = f >> 4, c4 = f & 15;
                if (c4 == 0) msk[row] = (v.z == 1.0f && v.w == 0.0f) ? 1u : 0u;
                uint2 pp;
                pp.x = packh2(v.x, v.y);
                pp.y = packh2(v.z, v.w);
                *reinterpret_cast<uint2*>(smb + SM_A1 + (uint32_t)(row * (LDA * 2) + c4 * 8)) = pp;
            }
        }
        __syncthreads();

        // ---- prefetch next tile (overlaps all compute below) ----
        int nt = tile + GRID_CTAS;
        if (nt < NTILES) {
            const float4* g = reinterpret_cast<const float4*>(obs + (size_t)nt * (TILE_M * 64));
            #pragma unroll
            for (int i = 0; i < 16; i++)
                cp16(sb + SM_XS + (uint32_t)(i * THREADS + tid) * 16, g + i * THREADS + tid);
        }
        CP_COMMIT();

        // ---- load A1 fragments (reused across all 4 N-chunks) ----
        uint32_t a1f[2][4][4];
        #pragma unroll
        for (int rb = 0; rb < 2; rb++)
            #pragma unroll
            for (int kb = 0; kb < 4; kb++)
                ldsm_x4(a1f[rb][kb],
                        sb + SM_A1 + (uint32_t)((wrow + rb * 16 + (l & 15)) * LDA
                                                + kb * 16 + (l >> 4) * 8) * 2);

        uint32_t m0[2], m1[2];
        #pragma unroll
        for (int rb = 0; rb < 2; rb++) {
            m0[rb] = msk[wrow + rb * 16 + (l >> 2)];
            m1[rb] = msk[wrow + rb * 16 + (l >> 2) + 8];
        }

        float acc2[2][8][4];
        #pragma unroll
        for (int rb = 0; rb < 2; rb++)
            #pragma unroll
            for (int nb = 0; nb < 8; nb++)
                #pragma unroll
                for (int q = 0; q < 4; q++) acc2[rb][nb][q] = 0.f;

        // ---- 4 chunks of 64 hidden cols: L1 mma -> relu/mask -> L2 mma ----
        #pragma unroll
        for (int c = 0; c < 4; c++) {
            float acc1[2][8][4];
            #pragma unroll
            for (int rb = 0; rb < 2; rb++)
                #pragma unroll
                for (int nb = 0; nb < 8; nb++)
                    #pragma unroll
                    for (int q = 0; q < 4; q++) acc1[rb][nb][q] = 0.f;

            #pragma unroll
            for (int p = 0; p < 4; p++)
                #pragma unroll
                for (int kb = 0; kb < 4; kb++) {
                    uint32_t b[4];
                    ldsm_x4t(b, sb + SM_B1 + (uint32_t)((kb * 16 + (l & 15)) * LD1
                                                        + c * 64 + p * 16 + (l >> 4) * 8) * 2);
                    #pragma unroll
                    for (int rb = 0; rb < 2; rb++) {
                        mma16816(acc1[rb][2 * p],     a1f[rb][kb], b[0], b[1]);
                        mma16816(acc1[rb][2 * p + 1], a1f[rb][kb], b[2], b[3]);
                    }
                }

            // epilogue: bias + relu + routing mask -> fp16 A2 fragments (in regs)
            uint32_t a2[2][4][4];
            #pragma unroll
            for (int rb = 0; rb < 2; rb++) {
                bool k0 = (c < 2) ? (m0[rb] != 0) : (m0[rb] == 0);
                bool k1 = (c < 2) ? (m1[rb] != 0) : (m1[rb] == 0);
                #pragma unroll
                for (int nb = 0; nb < 8; nb++) {
                    int colb = c * 64 + nb * 8 + 2 * (l & 3);
                    float2 bi = *reinterpret_cast<const float2*>(b1cat + colb);
                    float v0 = k0 ? fmaxf(acc1[rb][nb][0] + bi.x, 0.f) : 0.f;
                    float v1 = k0 ? fmaxf(acc1[rb][nb][1] + bi.y, 0.f) : 0.f;
                    float v2 = k1 ? fmaxf(acc1[rb][nb][2] + bi.x, 0.f) : 0.f;
                    float v3 = k1 ? fmaxf(acc1[rb][nb][3] + bi.y, 0.f) : 0.f;
                    a2[rb][nb >> 1][(nb & 1) * 2 + 0] = packh2(v0, v1);
                    a2[rb][nb >> 1][(nb & 1) * 2 + 1] = packh2(v2, v3);
                }
            }

            // layer-2 partial accumulation over this 64-wide k-chunk
            #pragma unroll
            for (int p2 = 0; p2 < 4; p2++)
                #pragma unroll
                for (int kb = 0; kb < 4; kb++) {
                    uint32_t b[4];
                    ldsm_x4t(b, sb + SM_B2 + (uint32_t)((c * 64 + kb * 16 + (l & 15)) * LD2
                                                        + p2 * 16 + (l >> 4) * 8) * 2);
                    #pragma unroll
                    for (int rb = 0; rb < 2; rb++) {
                        mma16816(acc2[rb][2 * p2],     a2[rb][kb], b[0], b[1]);
                        mma16816(acc2[rb][2 * p2 + 1], a2[rb][kb], b[2], b[3]);
                    }
                }
        }

        // ---- store: routed layer-2 bias + write out ----
        #pragma unroll
        for (int rb = 0; rb < 2; rb++) {
            const float* bb0 = b2s + (m0[rb] ? 0 : 64);
            const float* bb1 = b2s + (m1[rb] ? 0 : 64);
            size_t g0 = ((size_t)tile * TILE_M + wrow + rb * 16 + (l >> 2)) * 64;
            size_t g1 = g0 + 8 * 64;
            #pragma unroll
            for (int nb = 0; nb < 8; nb++) {
                int cb = nb * 8 + (l & 3) * 2;
                float2 o0, o1;
                o0.x = acc2[rb][nb][0] + bb0[cb];
                o0.y = acc2[rb][nb][1] + bb0[cb + 1];
                o1.x = acc2[rb][nb][2] + bb1[cb];
                o1.y = acc2[rb][nb][3] + bb1[cb + 1];
                *reinterpret_cast<float2*>(out + g0 + cb) = o0;
                *reinterpret_cast<float2*>(out + g1 + cb) = o1;
            }
        }
    }
}

// ---------------- launch ----------------
extern "C" void kernel_launch(void* const* d_in, const int* in_sizes, int n_in,
                              void* d_out, int out_size) {
    (void)in_sizes; (void)n_in; (void)out_size;
    cudaFuncSetAttribute(STAR_moe_mlp_kernel,
                         cudaFuncAttributeMaxDynamicSharedMemorySize, SMEM_BYTES);
    STAR_moe_mlp_kernel<<<GRID_CTAS, THREADS, SMEM_BYTES>>>(
        (const float*)d_in[0],
        (const float*)d_in[1],  (const float*)d_in[2],
        (const float*)d_in[3],  (const float*)d_in[4],
        (const float*)d_in[5],  (const float*)d_in[6],
        (const float*)d_in[7],  (const float*)d_in[8],
        (const float*)d_in[9],  (const float*)d_in[10],
        (const float*)d_in[11], (const float*)d_in[12],
        (float*)d_out);
}

// round 3
// speedup vs baseline: 1.0902x; 1.0902x over previous
#include <cuda_runtime.h>
#include <cuda_fp16.h>
#include <cstdint>

// ---------------- constants ----------------
#define GRID_CTAS 148
#define THREADS   512
#define TILE_M    256
#define NROWS     1048576
#define NTILES    (NROWS / TILE_M)      // 4096

// smem byte offsets (from 1024-aligned dynamic base)
#define SM_MASK   0                     // 256 u32 row routing flags
#define SM_B1CAT  1024                  // 256 f32 layer-1 biases (concat)
#define SM_B2S    2048                  // 128 f32 layer-2 biases (b | c)
#define SM_B1     4096                  // W1cat fp16 [k=64][n=256] ld=264 -> 33792 B
#define SM_B2     (SM_B1 + 33792)       // W2cat fp16 [k=256][n=64] ld=72  -> 36864 B
#define SM_A1     (SM_B2 + 36864)       // obs tile fp16 [256][64] ld=72   -> 36864 B
#define SM_XS     (SM_A1 + 36864)       // obs tile fp32 staging [256][64] -> 65536 B
#define SM_END    (SM_XS + 65536)
#define SMEM_BYTES (SM_END + 1024)

#define LD1 264   // halfs per row of B1
#define LD2 72    // halfs per row of B2
#define LDA 72    // halfs per row of A1

// ---------------- ptx helpers ----------------
__device__ __forceinline__ uint32_t s2u(const void* p) {
    uint32_t a;
    asm("{ .reg .u64 t; cvta.to.shared.u64 t, %1; cvt.u32.u64 %0, t; }" : "=r"(a) : "l"(p));
    return a;
}
__device__ __forceinline__ void ldsm_x4(uint32_t* r, uint32_t addr) {
    asm volatile("ldmatrix.sync.aligned.m8n8.x4.shared.b16 {%0,%1,%2,%3}, [%4];"
                 : "=r"(r[0]), "=r"(r[1]), "=r"(r[2]), "=r"(r[3]) : "r"(addr));
}
__device__ __forceinline__ void ldsm_x4t(uint32_t* r, uint32_t addr) {
    asm volatile("ldmatrix.sync.aligned.m8n8.x4.trans.shared.b16 {%0,%1,%2,%3}, [%4];"
                 : "=r"(r[0]), "=r"(r[1]), "=r"(r[2]), "=r"(r[3]) : "r"(addr));
}
__device__ __forceinline__ void mma16816(float* d, const uint32_t* a, uint32_t b0, uint32_t b1) {
    asm volatile("mma.sync.aligned.m16n8k16.row.col.f32.f16.f16.f32 "
                 "{%0,%1,%2,%3}, {%4,%5,%6,%7}, {%8,%9}, {%0,%1,%2,%3};"
                 : "+f"(d[0]), "+f"(d[1]), "+f"(d[2]), "+f"(d[3])
                 : "r"(a[0]), "r"(a[1]), "r"(a[2]), "r"(a[3]), "r"(b0), "r"(b1));
}
__device__ __forceinline__ void cp16(uint32_t dst, const void* src) {
    asm volatile("cp.async.cg.shared.global [%0], [%1], 16;" :: "r"(dst), "l"(src));
}
#define CP_COMMIT() asm volatile("cp.async.commit_group;" ::: "memory")
#define CP_WAIT0()  asm volatile("cp.async.wait_group 0;" ::: "memory")

__device__ __forceinline__ uint32_t packh2(float x, float y) {
    __half2 h = __floats2half2_rn(x, y);
    return *reinterpret_cast<uint32_t*>(&h);
}

// ---------------- kernel ----------------
extern "C" __global__ void __launch_bounds__(THREADS, 1)
STAR_moe_mlp_kernel(
    const float* __restrict__ obs,
    const float* __restrict__ W1b, const float* __restrict__ b1b,
    const float* __restrict__ W2b, const float* __restrict__ b2b,
    const float* __restrict__ W1c, const float* __restrict__ b1c,
    const float* __restrict__ W2c, const float* __restrict__ b2c,
    const float* __restrict__ W1p, const float* __restrict__ b1p,
    const float* __restrict__ W2p, const float* __restrict__ b2p,
    float* __restrict__ out)
{
    extern __shared__ char smem_raw[];
    uint32_t sb0 = s2u(smem_raw);
    uint32_t sb  = (sb0 + 1023u) & ~1023u;
    char* smb = smem_raw + (sb - sb0);

    const int tid = threadIdx.x;
    const int wid = tid >> 5, l = tid & 31;
    const int wrow = wid * 16;                 // warp's 16-row base within tile

    uint32_t* msk   = reinterpret_cast<uint32_t*>(smb + SM_MASK);
    float*    b1cat = reinterpret_cast<float*>(smb + SM_B1CAT);
    float*    b2s   = reinterpret_cast<float*>(smb + SM_B2S);

    // ---- one-time setup: fused weights (fp16) + biases into SMEM ----
    for (int idx = tid; idx < 64 * 256; idx += THREADS) {       // B1: [k=64][n=256]
        int k = idx >> 8, n = idx & 255;
        float w = (n < 128) ? W1b[k * 128 + n] * W1p[k * 128 + n]
                            : W1c[k * 128 + (n - 128)] * W1p[k * 128 + (n - 128)];
        *reinterpret_cast<__half*>(smb + SM_B1 + (uint32_t)(k * LD1 + n) * 2) = __float2half_rn(w);
    }
    for (int idx = tid; idx < 256 * 64; idx += THREADS) {       // B2: [k=256][n=64]
        int k = idx >> 6, n = idx & 63;
        float w = (k < 128) ? W2b[k * 64 + n] * W2p[k * 64 + n]
                            : W2c[(k - 128) * 64 + n] * W2p[(k - 128) * 64 + n];
        *reinterpret_cast<__half*>(smb + SM_B2 + (uint32_t)(k * LD2 + n) * 2) = __float2half_rn(w);
    }
    for (int i = tid; i < 256; i += THREADS)
        b1cat[i] = (i < 128) ? b1b[i] + b1p[i] : b1c[i - 128] + b1p[i - 128];
    for (int i = tid; i < 128; i += THREADS)
        b2s[i] = (i < 64) ? b2b[i] + b2p[i] : b2c[i - 64] + b2p[i - 64];

    // ---- prologue: async-load first obs tile (fp32 staging) ----
    {
        const float4* g = reinterpret_cast<const float4*>(obs + (size_t)blockIdx.x * (TILE_M * 64));
        #pragma unroll
        for (int i = 0; i < 8; i++)
            cp16(sb + SM_XS + (uint32_t)(i * THREADS + tid) * 16, g + i * THREADS + tid);
    }
    CP_COMMIT();

    for (int it = 0;; it++) {
        int tile = blockIdx.x + it * GRID_CTAS;
        if (tile >= NTILES) break;

        // ---- convert staged fp32 -> fp16 A1 (+ routing masks) ----
        CP_WAIT0();
        __syncthreads();
        {
            const float4* xs = reinterpret_cast<const float4*>(smb + SM_XS);
            #pragma unroll
            for (int i = 0; i < 8; i++) {
                int f = i * THREADS + tid;
                float4 v = xs[f];
                int row = f >> 4, c4 = f & 15;
                if (c4 == 0) msk[row] = (v.z == 1.0f && v.w == 0.0f) ? 1u : 0u;
                uint2 pp;
                pp.x = packh2(v.x, v.y);
                pp.y = packh2(v.z, v.w);
                *reinterpret_cast<uint2*>(smb + SM_A1 + (uint32_t)(row * (LDA * 2) + c4 * 8)) = pp;
            }
        }
        __syncthreads();

        // ---- prefetch next tile (overlaps all compute below) ----
        int nt = tile + GRID_CTAS;
        if (nt < NTILES) {
            const float4* g = reinterpret_cast<const float4*>(obs + (size_t)nt * (TILE_M * 64));
            #pragma unroll
            for (int i = 0; i < 8; i++)
                cp16(sb + SM_XS + (uint32_t)(i * THREADS + tid) * 16, g + i * THREADS + tid);
        }
        CP_COMMIT();

        // ---- load A1 fragments (16 rows x k64, reused across all 4 N-chunks) ----
        uint32_t a1f[4][4];
        #pragma unroll
        for (int kb = 0; kb < 4; kb++)
            ldsm_x4(a1f[kb],
                    sb + SM_A1 + (uint32_t)((wrow + (l & 15)) * LDA
                                            + kb * 16 + (l >> 4) * 8) * 2);

        uint32_t m0 = msk[wrow + (l >> 2)];
        uint32_t m1 = msk[wrow + (l >> 2) + 8];

        float acc2[8][4];
        #pragma unroll
        for (int nb = 0; nb < 8; nb++)
            #pragma unroll
            for (int q = 0; q < 4; q++) acc2[nb][q] = 0.f;

        // ---- 4 chunks of 64 hidden cols: L1 mma -> relu/mask -> L2 mma ----
        #pragma unroll
        for (int c = 0; c < 4; c++) {
            float acc1[8][4];
            #pragma unroll
            for (int nb = 0; nb < 8; nb++)
                #pragma unroll
                for (int q = 0; q < 4; q++) acc1[nb][q] = 0.f;

            #pragma unroll
            for (int p = 0; p < 4; p++)
                #pragma unroll
                for (int kb = 0; kb < 4; kb++) {
                    uint32_t b[4];
                    ldsm_x4t(b, sb + SM_B1 + (uint32_t)((kb * 16 + (l & 15)) * LD1
                                                        + c * 64 + p * 16 + (l >> 4) * 8) * 2);
                    mma16816(acc1[2 * p],     a1f[kb], b[0], b[1]);
                    mma16816(acc1[2 * p + 1], a1f[kb], b[2], b[3]);
                }

            // epilogue: bias + relu + routing mask -> fp16 A2 fragments (in regs)
            uint32_t a2[4][4];
            {
                bool k0 = (c < 2) ? (m0 != 0) : (m0 == 0);
                bool k1 = (c < 2) ? (m1 != 0) : (m1 == 0);
                #pragma unroll
                for (int nb = 0; nb < 8; nb++) {
                    int colb = c * 64 + nb * 8 + 2 * (l & 3);
                    float2 bi = *reinterpret_cast<const float2*>(b1cat + colb);
                    float v0 = k0 ? fmaxf(acc1[nb][0] + bi.x, 0.f) : 0.f;
                    float v1 = k0 ? fmaxf(acc1[nb][1] + bi.y, 0.f) : 0.f;
                    float v2 = k1 ? fmaxf(acc1[nb][2] + bi.x, 0.f) : 0.f;
                    float v3 = k1 ? fmaxf(acc1[nb][3] + bi.y, 0.f) : 0.f;
                    a2[nb >> 1][(nb & 1) * 2 + 0] = packh2(v0, v1);
                    a2[nb >> 1][(nb & 1) * 2 + 1] = packh2(v2, v3);
                }
            }

            // layer-2 partial accumulation over this 64-wide k-chunk
            #pragma unroll
            for (int p2 = 0; p2 < 4; p2++)
                #pragma unroll
                for (int kb = 0; kb < 4; kb++) {
                    uint32_t b[4];
                    ldsm_x4t(b, sb + SM_B2 + (uint32_t)((c * 64 + kb * 16 + (l & 15)) * LD2
                                                        + p2 * 16 + (l >> 4) * 8) * 2);
                    mma16816(acc2[2 * p2],     a2[kb], b[0], b[1]);
                    mma16816(acc2[2 * p2 + 1], a2[kb], b[2], b[3]);
                }
        }

        // ---- store: routed layer-2 bias + write out ----
        {
            const float* bb0 = b2s + (m0 ? 0 : 64);
            const float* bb1 = b2s + (m1 ? 0 : 64);
            size_t g0 = ((size_t)tile * TILE_M + wrow + (l >> 2)) * 64;
            size_t g1 = g0 + 8 * 64;
            #pragma unroll
            for (int nb = 0; nb < 8; nb++) {
                int cb = nb * 8 + (l & 3) * 2;
                float2 o0, o1;
                o0.x = acc2[nb][0] + bb0[cb];
                o0.y = acc2[nb][1] + bb0[cb + 1];
                o1.x = acc2[nb][2] + bb1[cb];
                o1.y = acc2[nb][3] + bb1[cb + 1];
                *reinterpret_cast<float2*>(out + g0 + cb) = o0;
                *reinterpret_cast<float2*>(out + g1 + cb) = o1;
            }
        }
    }
}

// ---------------- launch ----------------
extern "C" void kernel_launch(void* const* d_in, const int* in_sizes, int n_in,
                              void* d_out, int out_size) {
    (void)in_sizes; (void)n_in; (void)out_size;
    cudaFuncSetAttribute(STAR_moe_mlp_kernel,
                         cudaFuncAttributeMaxDynamicSharedMemorySize, SMEM_BYTES);
    STAR_moe_mlp_kernel<<<GRID_CTAS, THREADS, SMEM_BYTES>>>(
        (const float*)d_in[0],
        (const float*)d_in[1],  (const float*)d_in[2],
        (const float*)d_in[3],  (const float*)d_in[4],
        (const float*)d_in[5],  (const float*)d_in[6],
        (const float*)d_in[7],  (const float*)d_in[8],
        (const float*)d_in[9],  (const float*)d_in[10],
        (const float*)d_in[11], (const float*)d_in[12],
        (float*)d_out);
}

// round 5
// speedup vs baseline: 1.4175x; 1.3002x over previous
#include <cuda_runtime.h>
#include <cuda_fp16.h>
#include <cstdint>

// ---------------- constants ----------------
#define GRID_CTAS 148
#define THREADS   512
#define TILE_M    240                   // 15 slots of 16 rows
#define NROWS     1048576
#define NTILES    4370                  // ceil(NROWS/240); last tile = 16 rows
#define NF4       16777216              // NROWS*16 float4s in obs

// smem byte offsets (from 1024-aligned dynamic base)
#define SM_PERM   0                     // 240 int: pos -> (row<<1)|isb, -1 invalid
#define SM_CNT    960                   // 2 int counters
#define SM_B1CAT  1024                  // 256 f32 layer-1 biases (b|c)
#define SM_B2S    2048                  // 128 f32 layer-2 biases (b|c)
#define SM_B1     4096                  // W1cat fp16 [k=64][n=256] ld=264 -> 33792 B
#define SM_B2     (SM_B1 + 33792)       // W2cat fp16 [k=256][n=64] ld=72  -> 36864 B
#define SM_A1     (SM_B2 + 36864)       // permuted tile fp16 [240][64] ld=72 -> 34560 B
#define SM_XS     (SM_A1 + 34560)       // obs tile fp32 staging [240][64]   -> 61440 B
#define SM_END    (SM_XS + 61440)
#define SMEM_BYTES (SM_END + 1024)

#define LD1 264   // halfs per row of B1
#define LD2 72    // halfs per row of B2
#define LDA 72    // halfs per row of A1

// ---------------- ptx helpers ----------------
__device__ __forceinline__ uint32_t s2u(const void* p) {
    uint32_t a;
    asm("{ .reg .u64 t; cvta.to.shared.u64 t, %1; cvt.u32.u64 %0, t; }" : "=r"(a) : "l"(p));
    return a;
}
__device__ __forceinline__ void ldsm_x4(uint32_t* r, uint32_t addr) {
    asm volatile("ldmatrix.sync.aligned.m8n8.x4.shared.b16 {%0,%1,%2,%3}, [%4];"
                 : "=r"(r[0]), "=r"(r[1]), "=r"(r[2]), "=r"(r[3]) : "r"(addr));
}
__device__ __forceinline__ void ldsm_x4t(uint32_t* r, uint32_t addr) {
    asm volatile("ldmatrix.sync.aligned.m8n8.x4.trans.shared.b16 {%0,%1,%2,%3}, [%4];"
                 : "=r"(r[0]), "=r"(r[1]), "=r"(r[2]), "=r"(r[3]) : "r"(addr));
}
__device__ __forceinline__ void mma16816(float* d, const uint32_t* a, uint32_t b0, uint32_t b1) {
    asm volatile("mma.sync.aligned.m16n8k16.row.col.f32.f16.f16.f32 "
                 "{%0,%1,%2,%3}, {%4,%5,%6,%7}, {%8,%9}, {%0,%1,%2,%3};"
                 : "+f"(d[0]), "+f"(d[1]), "+f"(d[2]), "+f"(d[3])
                 : "r"(a[0]), "r"(a[1]), "r"(a[2]), "r"(a[3]), "r"(b0), "r"(b1));
}
__device__ __forceinline__ void cp16(uint32_t dst, const void* src) {
    asm volatile("cp.async.cg.shared.global [%0], [%1], 16;" :: "r"(dst), "l"(src));
}
#define CP_COMMIT() asm volatile("cp.async.commit_group;" ::: "memory")
#define CP_WAIT0()  asm volatile("cp.async.wait_group 0;" ::: "memory")

__device__ __forceinline__ uint32_t packh2(float x, float y) {
    __half2 h = __floats2half2_rn(x, y);
    return *reinterpret_cast<uint32_t*>(&h);
}

// ---------------- kernel ----------------
extern "C" __global__ void __launch_bounds__(THREADS, 1)
STAR_moe_mlp_kernel(
    const float* __restrict__ obs,
    const float* __restrict__ W1b, const float* __restrict__ b1b,
    const float* __restrict__ W2b, const float* __restrict__ b2b,
    const float* __restrict__ W1c, const float* __restrict__ b1c,
    const float* __restrict__ W2c, const float* __restrict__ b2c,
    const float* __restrict__ W1p, const float* __restrict__ b1p,
    const float* __restrict__ W2p, const float* __restrict__ b2p,
    float* __restrict__ out)
{
    extern __shared__ char smem_raw[];
    uint32_t sb0 = s2u(smem_raw);
    uint32_t sb  = (sb0 + 1023u) & ~1023u;
    char* smb = smem_raw + (sb - sb0);

    const int tid = threadIdx.x;
    const int wid = tid >> 5, l = tid & 31;

    int*      perm  = reinterpret_cast<int*>(smb + SM_PERM);
    int*      cnts  = reinterpret_cast<int*>(smb + SM_CNT);
    float*    b1cat = reinterpret_cast<float*>(smb + SM_B1CAT);
    float*    b2s   = reinterpret_cast<float*>(smb + SM_B2S);

    // ---- one-time setup: fused weights (fp16) + biases into SMEM ----
    for (int idx = tid; idx < 64 * 256; idx += THREADS) {       // B1: [k=64][n=256] (b|c)
        int k = idx >> 8, n = idx & 255;
        float w = (n < 128) ? W1b[k * 128 + n] * W1p[k * 128 + n]
                            : W1c[k * 128 + (n - 128)] * W1p[k * 128 + (n - 128)];
        *reinterpret_cast<__half*>(smb + SM_B1 + (uint32_t)(k * LD1 + n) * 2) = __float2half_rn(w);
    }
    for (int idx = tid; idx < 256 * 64; idx += THREADS) {       // B2: [k=256][n=64] (b|c in k)
        int k = idx >> 6, n = idx & 63;
        float w = (k < 128) ? W2b[k * 64 + n] * W2p[k * 64 + n]
                            : W2c[(k - 128) * 64 + n] * W2p[(k - 128) * 64 + n];
        *reinterpret_cast<__half*>(smb + SM_B2 + (uint32_t)(k * LD2 + n) * 2) = __float2half_rn(w);
    }
    for (int i = tid; i < 256; i += THREADS)
        b1cat[i] = (i < 128) ? b1b[i] + b1p[i] : b1c[i - 128] + b1p[i - 128];
    for (int i = tid; i < 128; i += THREADS)
        b2s[i] = (i < 64) ? b2b[i] + b2p[i] : b2c[i - 64] + b2p[i - 64];

    // ---- prologue: async-load first obs tile (fp32 staging); tiles <148 are full ----
    {
        const float4* g = reinterpret_cast<const float4*>(obs + (size_t)blockIdx.x * (TILE_M * 64));
        #pragma unroll
        for (int i = 0; i < 8; i++) {
            int f = i * THREADS + tid;
            if (f < TILE_M * 16) cp16(sb + SM_XS + (uint32_t)f * 16, g + f);
        }
    }
    CP_COMMIT();

    for (int it = 0;; it++) {
        int tile = blockIdx.x + it * GRID_CTAS;
        if (tile >= NTILES) break;

        CP_WAIT0();
        __syncthreads();                       // staging ready; prev-tile stores done

        // ---- init permutation state ----
        if (tid < TILE_M) perm[tid] = -1;
        if (tid == 0) { cnts[0] = 0; cnts[1] = 0; }
        __syncthreads();

        // ---- mask + permutation pass: b-rows pack low, c-rows pack high ----
        if (tid < TILE_M) {
            bool real = ((size_t)tile * TILE_M + tid) < (size_t)NROWS;
            if (real) {
                float2 v = *reinterpret_cast<const float2*>(smb + SM_XS + tid * 256 + 8);
                bool isb = (v.x == 1.0f && v.y == 0.0f);
                int pos = isb ? atomicAdd(&cnts[0], 1)
                              : (TILE_M - 1) - atomicAdd(&cnts[1], 1);
                perm[pos] = (tid << 1) | (isb ? 1 : 0);
            }
        }
        __syncthreads();

        // ---- convert pass: gather fp32 rows by position -> fp16 A1 (permuted) ----
        {
            const float4* xs4 = reinterpret_cast<const float4*>(smb + SM_XS);
            #pragma unroll
            for (int i = 0; i < 8; i++) {
                int f = i * THREADS + tid;
                if (f < TILE_M * 16) {
                    int p = f >> 4, c4 = f & 15;
                    int v = perm[p];
                    if (v >= 0) {
                        float4 x = xs4[(v >> 1) * 16 + c4];
                        uint2 pp;
                        pp.x = packh2(x.x, x.y);
                        pp.y = packh2(x.z, x.w);
                        *reinterpret_cast<uint2*>(smb + SM_A1 + (uint32_t)(p * (LDA * 2) + c4 * 8)) = pp;
                    }
                }
            }
        }
        __syncthreads();

        // ---- prefetch next tile (guarded; overlaps compute) ----
        int nt = tile + GRID_CTAS;
        if (nt < NTILES) {
            const float4* g = reinterpret_cast<const float4*>(obs + (size_t)nt * (TILE_M * 64));
            int lim = NF4 - nt * (TILE_M * 16);
            if (lim > TILE_M * 16) lim = TILE_M * 16;
            #pragma unroll
            for (int i = 0; i < 8; i++) {
                int f = i * THREADS + tid;
                if (f < lim) cp16(sb + SM_XS + (uint32_t)f * 16, g + f);
            }
        }
        CP_COMMIT();

        // ---- slot assignment: one 16-row single-expert slot per warp ----
        int cnt_b = cnts[0], cnt_c = cnts[1];
        int cstart = TILE_M - cnt_c;
        int sb_slots = (cnt_b + 15) >> 4;
        int slot, e;
        bool active;
        if (wid < sb_slots) { slot = wid; e = 1; active = true; }
        else { slot = (cstart >> 4) + (wid - sb_slots); e = 0; active = (slot <= 14); }

        if (active) {
            // expert half: b (e=1) lives at hidden cols [0,128), c (e=0) at [128,256)
            const int ebase = e ? 0 : 128;

            // A fragments: rows slot*16..+15, k=64
            uint32_t a1f[4][4];
            #pragma unroll
            for (int kb = 0; kb < 4; kb++)
                ldsm_x4(a1f[kb],
                        sb + SM_A1 + (uint32_t)((slot * 16 + (l & 15)) * LDA
                                                + kb * 16 + (l >> 4) * 8) * 2);

            float acc2[8][4];
            #pragma unroll
            for (int nbt = 0; nbt < 8; nbt++)
                #pragma unroll
                for (int q = 0; q < 4; q++) acc2[nbt][q] = 0.f;

            // ---- 2 chunks of 64 hidden cols (this expert only) ----
            #pragma unroll
            for (int c = 0; c < 2; c++) {
                int hbase = ebase + c * 64;
                float acc1[8][4];
                #pragma unroll
                for (int nbt = 0; nbt < 8; nbt++)
                    #pragma unroll
                    for (int q = 0; q < 4; q++) acc1[nbt][q] = 0.f;

                #pragma unroll
                for (int p = 0; p < 4; p++)
                    #pragma unroll
                    for (int kb = 0; kb < 4; kb++) {
                        uint32_t b[4];
                        ldsm_x4t(b, sb + SM_B1 + (uint32_t)((kb * 16 + (l & 15)) * LD1
                                                            + hbase + p * 16 + (l >> 4) * 8) * 2);
                        mma16816(acc1[2 * p],     a1f[kb], b[0], b[1]);
                        mma16816(acc1[2 * p + 1], a1f[kb], b[2], b[3]);
                    }

                // bias + relu -> fp16 A2 fragments (expert known, no mask)
                uint32_t a2[4][4];
                #pragma unroll
                for (int nbt = 0; nbt < 8; nbt++) {
                    int colb = hbase + nbt * 8 + 2 * (l & 3);
                    float2 bi = *reinterpret_cast<const float2*>(b1cat + colb);
                    float v0 = fmaxf(acc1[nbt][0] + bi.x, 0.f);
                    float v1 = fmaxf(acc1[nbt][1] + bi.y, 0.f);
                    float v2 = fmaxf(acc1[nbt][2] + bi.x, 0.f);
                    float v3 = fmaxf(acc1[nbt][3] + bi.y, 0.f);
                    a2[nbt >> 1][(nbt & 1) * 2 + 0] = packh2(v0, v1);
                    a2[nbt >> 1][(nbt & 1) * 2 + 1] = packh2(v2, v3);
                }

                // layer-2 partial accumulation over this 64-wide k-chunk
                #pragma unroll
                for (int p2 = 0; p2 < 4; p2++)
                    #pragma unroll
                    for (int kb = 0; kb < 4; kb++) {
                        uint32_t b[4];
                        ldsm_x4t(b, sb + SM_B2 + (uint32_t)((hbase + kb * 16 + (l & 15)) * LD2
                                                            + p2 * 16 + (l >> 4) * 8) * 2);
                        mma16816(acc2[2 * p2],     a2[kb], b[0], b[1]);
                        mma16816(acc2[2 * p2 + 1], a2[kb], b[2], b[3]);
                    }
            }

            // ---- store: routed bias, scatter by perm, gate overlap/invalid rows ----
            {
                const float* bb = b2s + (e ? 0 : 64);
                int p0 = slot * 16 + (l >> 2), p1 = p0 + 8;
                int v0 = perm[p0], v1 = perm[p1];
                bool s0 = (v0 >= 0) && ((v0 & 1) == e);
                bool s1 = (v1 >= 0) && ((v1 & 1) == e);
                size_t base = (size_t)tile * TILE_M;
                float* o0 = out + (base + (size_t)(v0 >> 1)) * 64;
                float* o1 = out + (base + (size_t)(v1 >> 1)) * 64;
                #pragma unroll
                for (int nbt = 0; nbt < 8; nbt++) {
                    int cb = nbt * 8 + (l & 3) * 2;
                    if (s0) {
                        float2 o; o.x = acc2[nbt][0] + bb[cb]; o.y = acc2[nbt][1] + bb[cb + 1];
                        *reinterpret_cast<float2*>(o0 + cb) = o;
                    }
                    if (s1) {
                        float2 o; o.x = acc2[nbt][2] + bb[cb]; o.y = acc2[nbt][3] + bb[cb + 1];
                        *reinterpret_cast<float2*>(o1 + cb) = o;
                    }
                }
            }
        }
    }
}

// ---------------- launch ----------------
extern "C" void kernel_launch(void* const* d_in, const int* in_sizes, int n_in,
                              void* d_out, int out_size) {
    (void)in_sizes; (void)n_in; (void)out_size;
    cudaFuncSetAttribute(STAR_moe_mlp_kernel,
                         cudaFuncAttributeMaxDynamicSharedMemorySize, SMEM_BYTES);
    STAR_moe_mlp_kernel<<<GRID_CTAS, THREADS, SMEM_BYTES>>>(
        (const float*)d_in[0],
        (const float*)d_in[1],  (const float*)d_in[2],
        (const float*)d_in[3],  (const float*)d_in[4],
        (const float*)d_in[5],  (const float*)d_in[6],
        (const float*)d_in[7],  (const float*)d_in[8],
        (const float*)d_in[9],  (const float*)d_in[10],
        (const float*)d_in[11], (const float*)d_in[12],
        (float*)d_out);
}